// round 7
// baseline (speedup 1.0000x reference)
#include <cuda_runtime.h>
#include <cstdint>

// ---------------------------------------------------------------------------
// Problem constants
// ---------------------------------------------------------------------------
#define K_VOL    27
#define M_PAIRS  100000
#define C_IN     64
#define C_OUT    64
#define N_IN     200000
#define N_OUT    200000

#define TILE_M   128
#define TILES_PER_K 782
#define TOTAL_TILES (K_VOL * TILES_PER_K)   // 21114
#define GRID_P   296
#define BASE_T   (TOTAL_TILES / GRID_P)     // 71
#define EXTRA_T  (TOTAL_TILES - GRID_P * BASE_T)  // 98

// Quantized scratch (device globals)
__device__ unsigned char g_Aq[(size_t)N_IN * 128];   // row: 64B hi-limb | 64B lo-limb
__device__ unsigned char g_Bq1[K_VOL * 4096];        // [k][co][ci] hi limb
__device__ unsigned char g_Bq0[K_VOL * 4096];        // [k][co][ci] lo limb

// ---------------------------------------------------------------------------
// smem layout (bytes)
//   buf0 : 128 rows * 144 = 18432          [0, 18432)
//   buf1 :                                  [18432, 36864)
//   Bq   : 2 limbs * 64 rows * 80 = 10240   [36864, 47104)
//   stage: 128 * 72 floats = 36864          [47104, 83968)
// ---------------------------------------------------------------------------
#define ASTRIDE   144
#define BUF_SZ    18432
#define BQ_OFF    36864
#define BQ_STRIDE 80          // 16B-aligned rows; banks 20r+c -> conflict-free
#define BQ_LIMB   5120
#define STAGE_OFF 47104
#define SMEM_BYTES 83968
#define STAGE_STRIDE 72       // floats

__device__ __forceinline__ uint32_t smem_u32(const void* p) {
    uint32_t a;
    asm("{ .reg .u64 t; cvta.to.shared.u64 t, %1; cvt.u32.u64 %0, t; }" : "=r"(a) : "l"(p));
    return a;
}

__device__ __forceinline__ void ldsm_x4(uint32_t* r, uint32_t addr) {
    asm volatile("ldmatrix.sync.aligned.m8n8.x4.shared.b16 {%0,%1,%2,%3}, [%4];"
                 : "=r"(r[0]), "=r"(r[1]), "=r"(r[2]), "=r"(r[3]) : "r"(addr));
}

__device__ __forceinline__ void imma16832(int* c, const uint32_t* a, uint32_t b0, uint32_t b1) {
    asm volatile(
        "mma.sync.aligned.m16n8k32.row.col.s32.s8.s8.s32 "
        "{%0,%1,%2,%3}, {%4,%5,%6,%7}, {%8,%9}, {%0,%1,%2,%3};"
        : "+r"(c[0]), "+r"(c[1]), "+r"(c[2]), "+r"(c[3])
        : "r"(a[0]), "r"(a[1]), "r"(a[2]), "r"(a[3]), "r"(b0), "r"(b1));
}

__device__ __forceinline__ void cp_async16(uint32_t dst, const void* src, uint32_t sz) {
    asm volatile("cp.async.cg.shared.global [%0], [%1], 16, %2;"
                 :: "r"(dst), "l"(src), "r"(sz) : "memory");
}

__device__ __forceinline__ void quant_split(float x, float scale, int& hi, int& lo) {
    float v = fminf(fmaxf(x * scale, -16255.0f), 16255.0f);
    int a16 = __float2int_rn(v);
    hi = (a16 + 64) >> 7;          // [-127, 127]
    lo = a16 - (hi << 7);          // [-64, 63]
}

// ---------------------------------------------------------------------------
// Kernel A: quantize features -> g_Aq (scale 2048)
// ---------------------------------------------------------------------------
__global__ void quant_feats(const float* __restrict__ in) {
    int t = blockIdx.x * blockDim.x + threadIdx.x;
    if (t >= N_IN * 4) return;
    const int row = t >> 2, q = t & 3;
    const float4* s = (const float4*)(in + (size_t)row * 64 + q * 16);
    uint32_t hw[4], lw[4];
    #pragma unroll
    for (int j = 0; j < 4; j++) {
        float4 v = s[j];
        int h0, l0, h1, l1, h2, l2, h3, l3;
        quant_split(v.x, 2048.0f, h0, l0);
        quant_split(v.y, 2048.0f, h1, l1);
        quant_split(v.z, 2048.0f, h2, l2);
        quant_split(v.w, 2048.0f, h3, l3);
        hw[j] = (h0 & 0xFF) | ((h1 & 0xFF) << 8) | ((h2 & 0xFF) << 16) | ((uint32_t)(h3 & 0xFF) << 24);
        lw[j] = (l0 & 0xFF) | ((l1 & 0xFF) << 8) | ((l2 & 0xFF) << 16) | ((uint32_t)(l3 & 0xFF) << 24);
    }
    *(uint4*)(g_Aq + (size_t)row * 128 + q * 16)      = *(uint4*)hw;
    *(uint4*)(g_Aq + (size_t)row * 128 + 64 + q * 16) = *(uint4*)lw;
}

// ---------------------------------------------------------------------------
// Kernel B: quantize + transpose weights -> g_Bq1/g_Bq0 [k][co][ci] (scale 16384)
// ---------------------------------------------------------------------------
__global__ void quant_weights(const float* __restrict__ W) {
    int idx = blockIdx.x * blockDim.x + threadIdx.x;
    if (idx >= K_VOL * 4096) return;
    const int k = idx >> 12, r = idx & 4095, ci = r >> 6, co = r & 63;
    int hi, lo;
    quant_split(W[idx], 16384.0f, hi, lo);
    g_Bq1[k * 4096 + co * 64 + ci] = (unsigned char)(hi & 0xFF);
    g_Bq0[k * 4096 + co * 64 + ci] = (unsigned char)(lo & 0xFF);
}

// ---------------------------------------------------------------------------
// Kernel C: out[row][c] = bias[c]
// ---------------------------------------------------------------------------
__global__ void init_bias_kernel(float* __restrict__ out, const float* __restrict__ bias,
                                 int total4) {
    const float4* b4 = (const float4*)bias;
    int idx = blockIdx.x * blockDim.x + threadIdx.x;
    int stride = gridDim.x * blockDim.x;
    for (int i = idx; i < total4; i += stride)
        ((float4*)out)[i] = b4[i & 15];
}

// ---------------------------------------------------------------------------
// nrow preload + A prefetch (rows are 128 bytes: hi|lo limbs)
// ---------------------------------------------------------------------------
__device__ __forceinline__ void load_nrow(const int* __restrict__ imap, int t, int tid,
                                          int nrow[4]) {
    const int k    = t / TILES_PER_K;
    const int m0   = (t % TILES_PER_K) * TILE_M;
    const int mrem = min(TILE_M, M_PAIRS - m0);
    const int* imk = imap + (size_t)k * M_PAIRS + m0;
    #pragma unroll
    for (int q = 0; q < 4; q++) {
        const int r = q * 32 + (tid >> 3);
        nrow[q] = (r < mrem) ? __ldg(&imk[r]) : -1;
    }
}

__device__ __forceinline__ void prefetch_A(uint32_t sbase, uint32_t bufoff, int tid,
                                           const int nrow[4]) {
    const int chunk = tid & 7;
    #pragma unroll
    for (int p = 0; p < 4; p++) {
        const int row = p * 32 + (tid >> 3);
        const int gr  = nrow[p];
        const char* src = (const char*)g_Aq + ((size_t)(gr < 0 ? 0 : gr)) * 128 + chunk * 16;
        cp_async16(sbase + bufoff + row * ASTRIDE + chunk * 16, src, gr >= 0 ? 16u : 0u);
    }
    asm volatile("cp.async.commit_group;" ::: "memory");
}

// ---------------------------------------------------------------------------
// Kernel D: persistent gather -> IMMA fixed-point -> scatter
// 256 threads, warp grid 4m x 2n (warp = m32 x n32)
// ---------------------------------------------------------------------------
__global__ __launch_bounds__(256, 2)
void conv_imma_kernel(const int* __restrict__ imap, const int* __restrict__ omap,
                      float* __restrict__ out) {
    extern __shared__ char smem[];
    const uint32_t sbase = smem_u32(smem);

    const int tid  = threadIdx.x;
    const int wid  = tid >> 5;
    const int lane = tid & 31;
    const int mi   = wid >> 1;
    const int ni   = wid & 1;

    const int b   = blockIdx.x;
    const int nt_ = BASE_T + (b < EXTRA_T);
    const int t0  = b * BASE_T + min(b, EXTRA_T);

    // A ldmatrix lane base: matrix i = lane/8 -> (row (i&1)*8 + lane%8, 16B col i/2)
    const int li = lane >> 3;
    const uint32_t a_lane = (uint32_t)((((li & 1) * 8) + (lane & 7)) * ASTRIDE + (li >> 1) * 16);
    // B frag lane base: BYTE offset into smem[] for this lane's b-frag word
    const uint32_t bq_lane = (uint32_t)(BQ_OFF + (32 * ni + (lane >> 2)) * BQ_STRIDE
                                        + (lane & 3) * 4);

    int kcur = -1;
    int nrow[4];
    load_nrow(imap, t0, tid, nrow);
    prefetch_A(sbase, 0, tid, nrow);
    if (nt_ > 1) load_nrow(imap, t0 + 1, tid, nrow);

    for (int i = 0; i < nt_; i++) {
        const int t    = t0 + i;
        const int k    = t / TILES_PER_K;
        const int m0   = (t % TILES_PER_K) * TILE_M;
        const int mrem = min(TILE_M, M_PAIRS - m0);
        const uint32_t bufoff = (uint32_t)(i & 1) * BUF_SZ;

        asm volatile("cp.async.wait_group 0;" ::: "memory");
        __syncthreads();    // A[t] ready; prior stage/scatter and Bq reads done

        // ---- k-change: load quantized B into smem (<= 2x per block) ----
        if (k != kcur) {
            kcur = k;
            #pragma unroll
            for (int p = 0; p < 2; p++) {
                const int task  = p * 256 + tid;
                const int chunk = task & 3;
                const int row   = (task >> 2) & 63;
                const int limb  = task >> 8;   // 0 = hi(g_Bq1), 1 = lo(g_Bq0)
                const uint4* src = (const uint4*)((limb ? g_Bq0 : g_Bq1)
                                                  + (size_t)k * 4096 + row * 64) + chunk;
                *(uint4*)(smem + BQ_OFF + limb * BQ_LIMB + row * BQ_STRIDE + chunk * 16) = *src;
            }
            __syncthreads();
        }

        if (i + 1 < nt_) prefetch_A(sbase, bufoff ^ BUF_SZ, tid, nrow);
        if (i + 2 < nt_) load_nrow(imap, t + 2, tid, nrow);

        // ---- omap preload ----
        int orow[8];
        {
            const int* omk = omap + (size_t)k * M_PAIRS + m0;
            #pragma unroll
            for (int p = 0; p < 8; p++) {
                const int r = p * 16 + (tid >> 4);
                orow[p] = (r < mrem) ? __ldg(&omk[r]) : -1;
            }
        }

        // ---- load A fragments (both limbs, held across phases) ----
        uint32_t a1f[2][2][4], a0f[2][2][4];   // [ms][kc][4]
        #pragma unroll
        for (int ms = 0; ms < 2; ms++)
            #pragma unroll
            for (int kc = 0; kc < 2; kc++) {
                const uint32_t base = sbase + bufoff + a_lane
                                      + (32 * mi + 16 * ms) * ASTRIDE + kc * 32;
                ldsm_x4(a1f[ms][kc], base);        // hi limb at byte 0
                ldsm_x4(a0f[ms][kc], base + 64);   // lo limb at byte 64
            }

        // ---- integer accumulator ----
        int T[2][4][4];
        #pragma unroll
        for (int ms = 0; ms < 2; ms++)
            #pragma unroll
            for (int ng = 0; ng < 4; ng++)
                #pragma unroll
                for (int j = 0; j < 4; j++)
                    T[ms][ng][j] = 0;

        uint32_t bf[2][4][2];   // [kc][ng][half]

        // load b1 (hi-limb) frags
        #pragma unroll
        for (int kc = 0; kc < 2; kc++)
            #pragma unroll
            for (int ng = 0; ng < 4; ng++) {
                const uint32_t off = bq_lane + ng * 8 * BQ_STRIDE + kc * 32;
                bf[kc][ng][0] = *(const uint32_t*)(smem + off);
                bf[kc][ng][1] = *(const uint32_t*)(smem + off + 16);
            }

        // P11 = a1*b1
        #pragma unroll
        for (int kc = 0; kc < 2; kc++)
            #pragma unroll
            for (int ms = 0; ms < 2; ms++)
                #pragma unroll
                for (int ng = 0; ng < 4; ng++)
                    imma16832(T[ms][ng], a1f[ms][kc], bf[kc][ng][0], bf[kc][ng][1]);
        // T <<= 7
        #pragma unroll
        for (int ms = 0; ms < 2; ms++)
            #pragma unroll
            for (int ng = 0; ng < 4; ng++)
                #pragma unroll
                for (int j = 0; j < 4; j++)
                    T[ms][ng][j] <<= 7;
        // += a0*b1
        #pragma unroll
        for (int kc = 0; kc < 2; kc++)
            #pragma unroll
            for (int ms = 0; ms < 2; ms++)
                #pragma unroll
                for (int ng = 0; ng < 4; ng++)
                    imma16832(T[ms][ng], a0f[ms][kc], bf[kc][ng][0], bf[kc][ng][1]);
        // load b0 (lo-limb) frags
        #pragma unroll
        for (int kc = 0; kc < 2; kc++)
            #pragma unroll
            for (int ng = 0; ng < 4; ng++) {
                const uint32_t off = bq_lane + BQ_LIMB + ng * 8 * BQ_STRIDE + kc * 32;
                bf[kc][ng][0] = *(const uint32_t*)(smem + off);
                bf[kc][ng][1] = *(const uint32_t*)(smem + off + 16);
            }
        // += a1*b0
        #pragma unroll
        for (int kc = 0; kc < 2; kc++)
            #pragma unroll
            for (int ms = 0; ms < 2; ms++)
                #pragma unroll
                for (int ng = 0; ng < 4; ng++)
                    imma16832(T[ms][ng], a1f[ms][kc], bf[kc][ng][0], bf[kc][ng][1]);
        // += (a0*b0 + 64) >> 7   (per-ms temp keeps register peak low)
        #pragma unroll
        for (int ms = 0; ms < 2; ms++) {
            int tmp[4][4];
            #pragma unroll
            for (int ng = 0; ng < 4; ng++)
                #pragma unroll
                for (int j = 0; j < 4; j++)
                    tmp[ng][j] = 0;
            #pragma unroll
            for (int kc = 0; kc < 2; kc++)
                #pragma unroll
                for (int ng = 0; ng < 4; ng++)
                    imma16832(tmp[ng], a0f[ms][kc], bf[kc][ng][0], bf[kc][ng][1]);
            #pragma unroll
            for (int ng = 0; ng < 4; ng++)
                #pragma unroll
                for (int j = 0; j < 4; j++)
                    T[ms][ng][j] += (tmp[ng][j] + 64) >> 7;
        }

        // ---- stage (convert s32 -> f32; scale 2^-18) ----
        {
            const float CSC = 3.814697265625e-6f;   // 2^-18
            float* stage = (float*)(smem + STAGE_OFF);
            const int g  = lane >> 2;
            const int tq = lane & 3;
            #pragma unroll
            for (int ms = 0; ms < 2; ms++)
                #pragma unroll
                for (int ng = 0; ng < 4; ng++) {
                    const int r0 = 32 * mi + 16 * ms + g;
                    const int c  = 32 * ni + ng * 8 + 2 * tq;
                    *(float2*)&stage[r0 * STAGE_STRIDE + c] =
                        make_float2((float)T[ms][ng][0] * CSC, (float)T[ms][ng][1] * CSC);
                    *(float2*)&stage[(r0 + 8) * STAGE_STRIDE + c] =
                        make_float2((float)T[ms][ng][2] * CSC, (float)T[ms][ng][3] * CSC);
                }
        }
        __syncthreads();

        // ---- scatter: 16 lanes per row, red.v4 ----
        {
            const float* stage = (const float*)(smem + STAGE_OFF);
            const int chunk = tid & 15;
            #pragma unroll
            for (int p = 0; p < 8; p++) {
                const int r = p * 16 + (tid >> 4);
                if (orow[p] >= 0) {
                    float4 v = *(const float4*)(stage + r * STAGE_STRIDE + chunk * 4);
                    asm volatile("red.global.add.v4.f32 [%0], {%1, %2, %3, %4};"
                                 :: "l"(out + (size_t)orow[p] * C_OUT + chunk * 4),
                                    "f"(v.x), "f"(v.y), "f"(v.z), "f"(v.w)
                                 : "memory");
                }
            }
        }
    }
}

// ---------------------------------------------------------------------------
// Launch
// ---------------------------------------------------------------------------
extern "C" void kernel_launch(void* const* d_in, const int* in_sizes, int n_in,
                              void* d_out, int out_size) {
    const float* in_feats = (const float*)d_in[0];
    const float* kernel   = (const float*)d_in[1];
    const float* bias     = (const float*)d_in[2];
    const int*   imap     = (const int*)d_in[3];
    const int*   omap     = (const int*)d_in[4];
    float* out = (float*)d_out;
    (void)in_sizes; (void)n_in; (void)out_size;

    cudaFuncSetAttribute(conv_imma_kernel, cudaFuncAttributeMaxDynamicSharedMemorySize,
                         SMEM_BYTES);

    quant_feats<<<(N_IN * 4 + 255) / 256, 256>>>(in_feats);
    quant_weights<<<(K_VOL * 4096 + 255) / 256, 256>>>(kernel);
    init_bias_kernel<<<2048, 256>>>(out, bias, N_OUT * C_OUT / 4);

    conv_imma_kernel<<<GRID_P, 256, SMEM_BYTES>>>(imap, omap, out);
}

// round 9
// speedup vs baseline: 2.7824x; 2.7824x over previous
#include <cuda_runtime.h>
#include <cuda_bf16.h>
#include <cstdint>

// ---------------------------------------------------------------------------
// Problem constants
// ---------------------------------------------------------------------------
#define K_VOL    27
#define M_PAIRS  100000
#define C_IN     64
#define C_OUT    64
#define N_IN     200000
#define N_OUT    200000

#define TILE_M   64
#define TILES_PER_K ((M_PAIRS + TILE_M - 1) / TILE_M)   // 1563
#define TOTAL_TILES (K_VOL * TILES_PER_K)               // 42201
#define GRID_P   592                                     // 4 blocks/SM * 148
#define BASE_T   (TOTAL_TILES / GRID_P)                  // 71
#define EXTRA_T  (TOTAL_TILES - GRID_P * BASE_T)         // 169

// bf16 hi/lo scratch (device globals: allocation-free scratch)
__device__ __nv_bfloat16 g_A_hi[(size_t)N_IN * C_IN];
__device__ __nv_bfloat16 g_A_lo[(size_t)N_IN * C_IN];
__device__ __nv_bfloat16 g_B_hi[K_VOL * C_IN * C_OUT];  // [k][co][ci]
__device__ __nv_bfloat16 g_B_lo[K_VOL * C_IN * C_OUT];

// ---------------------------------------------------------------------------
// smem layout (bytes), per block:
//   buf0 : A hi 64*144 + A lo 64*144 = 18432   [0, 18432)
//   buf1 :                                      [18432, 36864)
//   Bl   : 64*144 = 9216                        [36864, 46080)
//   stage: 4 warps * 16 rows * 36 floats = 9216 [46080, 55296)
// ---------------------------------------------------------------------------
#define ASTRIDE    144
#define LIMB_SZ    9216
#define BUF_SZ     18432
#define BL_OFF     36864
#define STAGE_OFF  46080
#define WSTAGE_SZ  2304      // bytes per warp (16 rows * 36 floats * 4)
#define SMEM_BYTES 55296
#define SSTRIDE    36        // floats per stage row

__device__ __forceinline__ uint32_t smem_u32(const void* p) {
    uint32_t a;
    asm("{ .reg .u64 t; cvta.to.shared.u64 t, %1; cvt.u32.u64 %0, t; }" : "=r"(a) : "l"(p));
    return a;
}

__device__ __forceinline__ void ldsm_x4(uint32_t* r, uint32_t addr) {
    asm volatile("ldmatrix.sync.aligned.m8n8.x4.shared.b16 {%0,%1,%2,%3}, [%4];"
                 : "=r"(r[0]), "=r"(r[1]), "=r"(r[2]), "=r"(r[3]) : "r"(addr));
}

__device__ __forceinline__ void mma16816(float* c,
                                         const uint32_t* a, uint32_t b0, uint32_t b1) {
    asm volatile(
        "mma.sync.aligned.m16n8k16.row.col.f32.bf16.bf16.f32 "
        "{%0,%1,%2,%3}, {%4,%5,%6,%7}, {%8,%9}, {%0,%1,%2,%3};"
        : "+f"(c[0]), "+f"(c[1]), "+f"(c[2]), "+f"(c[3])
        : "r"(a[0]), "r"(a[1]), "r"(a[2]), "r"(a[3]), "r"(b0), "r"(b1));
}

__device__ __forceinline__ void cp_async16(uint32_t dst, const void* src, uint32_t sz) {
    asm volatile("cp.async.cg.shared.global [%0], [%1], 16, %2;"
                 :: "r"(dst), "l"(src), "r"(sz) : "memory");
}

// ---------------------------------------------------------------------------
// Kernel A: split fp32 features into bf16 hi + lo
// ---------------------------------------------------------------------------
__global__ void split_feats_kernel(const float* __restrict__ in, int total4) {
    int idx = blockIdx.x * blockDim.x + threadIdx.x;
    int stride = gridDim.x * blockDim.x;
    const float4* in4 = (const float4*)in;
    __nv_bfloat162* hi2 = (__nv_bfloat162*)g_A_hi;
    __nv_bfloat162* lo2 = (__nv_bfloat162*)g_A_lo;
    for (int i = idx; i < total4; i += stride) {
        float4 v = in4[i];
        __nv_bfloat16 h0 = __float2bfloat16_rn(v.x);
        __nv_bfloat16 h1 = __float2bfloat16_rn(v.y);
        __nv_bfloat16 h2 = __float2bfloat16_rn(v.z);
        __nv_bfloat16 h3 = __float2bfloat16_rn(v.w);
        __nv_bfloat16 l0 = __float2bfloat16_rn(v.x - __bfloat162float(h0));
        __nv_bfloat16 l1 = __float2bfloat16_rn(v.y - __bfloat162float(h1));
        __nv_bfloat16 l2 = __float2bfloat16_rn(v.z - __bfloat162float(h2));
        __nv_bfloat16 l3 = __float2bfloat16_rn(v.w - __bfloat162float(h3));
        hi2[i * 2 + 0] = __halves2bfloat162(h0, h1);
        hi2[i * 2 + 1] = __halves2bfloat162(h2, h3);
        lo2[i * 2 + 0] = __halves2bfloat162(l0, l1);
        lo2[i * 2 + 1] = __halves2bfloat162(l2, l3);
    }
}

// ---------------------------------------------------------------------------
// Kernel B: split + transpose weights: g_B[k][co][ci] = split(W[k][ci][co])
// ---------------------------------------------------------------------------
__global__ void split_weights_kernel(const float* __restrict__ W) {
    int idx = blockIdx.x * blockDim.x + threadIdx.x;
    if (idx >= K_VOL * C_IN * C_OUT) return;
    int k  = idx / (C_IN * C_OUT);
    int r  = idx % (C_IN * C_OUT);
    int ci = r / C_OUT;
    int co = r % C_OUT;
    float x = W[idx];
    __nv_bfloat16 h = __float2bfloat16_rn(x);
    __nv_bfloat16 l = __float2bfloat16_rn(x - __bfloat162float(h));
    int didx = k * (C_IN * C_OUT) + co * C_IN + ci;
    g_B_hi[didx] = h;
    g_B_lo[didx] = l;
}

// ---------------------------------------------------------------------------
// Kernel C: out[row][c] = bias[c]
// ---------------------------------------------------------------------------
__global__ void init_bias_kernel(float* __restrict__ out, const float* __restrict__ bias,
                                 int total4) {
    const float4* b4 = (const float4*)bias;
    int idx = blockIdx.x * blockDim.x + threadIdx.x;
    int stride = gridDim.x * blockDim.x;
    for (int i = idx; i < total4; i += stride)
        ((float4*)out)[i] = b4[i & 15];
}

// ---------------------------------------------------------------------------
// nrow preload + A prefetch: 1024 cp.async 16B tasks (64 rows x 8 chunks x 2 limbs)
// thread serves rows 16q + (tid>>3), q = 0..3 (same rows for hi and lo)
// ---------------------------------------------------------------------------
__device__ __forceinline__ void load_nrow(const int* __restrict__ imap, int t, int tid,
                                          int nrow[4]) {
    const int k    = t / TILES_PER_K;
    const int m0   = (t % TILES_PER_K) * TILE_M;
    const int mrem = min(TILE_M, M_PAIRS - m0);
    const int* imk = imap + (size_t)k * M_PAIRS + m0;
    #pragma unroll
    for (int q = 0; q < 4; q++) {
        const int r = q * 16 + (tid >> 3);
        nrow[q] = (r < mrem) ? __ldg(&imk[r]) : -1;
    }
}

__device__ __forceinline__ void prefetch_A(uint32_t sbase, uint32_t bufoff, int tid,
                                           const int nrow[4]) {
    const int chunk = tid & 7;
    #pragma unroll
    for (int p = 0; p < 8; p++) {
        const int q   = p & 3;
        const int row = q * 16 + (tid >> 3);
        const bool lo = p >= 4;
        const int gr  = nrow[q];
        const char* src = (const char*)(lo ? g_A_lo : g_A_hi)
                          + ((size_t)(gr < 0 ? 0 : gr)) * 128 + chunk * 16;
        const uint32_t dst = sbase + bufoff + (lo ? LIMB_SZ : 0) + row * ASTRIDE + chunk * 16;
        cp_async16(dst, src, gr >= 0 ? 16u : 0u);   // sz=0 -> zero-fill
    }
    asm volatile("cp.async.commit_group;" ::: "memory");
}

// ---------------------------------------------------------------------------
// Kernel D: persistent gather -> bf16-split HMMA -> per-warp staged scatter
// 128 threads (4 warps: 2mi x 2ni), TILE_M = 64
// ---------------------------------------------------------------------------
__global__ __launch_bounds__(128, 4)
void conv_mma_kernel(const int* __restrict__ imap, const int* __restrict__ omap,
                     float* __restrict__ out) {
    extern __shared__ char smem[];
    const uint32_t sbase = smem_u32(smem);

    const int tid  = threadIdx.x;
    const int wid  = tid >> 5;
    const int lane = tid & 31;
    const int mi   = wid >> 1;      // 0..1 : rows 32*mi..+31
    const int ni   = wid & 1;       // 0..1 : cols 32*ni..+31

    const int b   = blockIdx.x;
    const int nt_ = BASE_T + (b < EXTRA_T);
    const int t0  = b * BASE_T + min(b, EXTRA_T);

    // ldmatrix lane offsets (identical to proven R5 mapping)
    const int li = lane >> 3;
    const uint32_t a_lane = (uint32_t)((((li & 1) * 8) + (lane & 7)) * ASTRIDE + (li >> 1) * 16);
    const int b_row  = (lane & 7) + ((lane >> 4) ? 8 : 0);
    const int b_koff = ((lane >> 3) & 1) * 8;

    uint32_t bh[4][2][4];           // weight-hi fragments: [kc][np][4]
    int kcur = -1;

    int nrow[4];
    load_nrow(imap, t0, tid, nrow);
    prefetch_A(sbase, 0, tid, nrow);
    if (nt_ > 1) load_nrow(imap, t0 + 1, tid, nrow);

    float* swarp = (float*)(smem + STAGE_OFF + wid * WSTAGE_SZ);

    for (int i = 0; i < nt_; i++) {
        const int t    = t0 + i;
        const int k    = t / TILES_PER_K;
        const int m0   = (t % TILES_PER_K) * TILE_M;
        const int mrem = min(TILE_M, M_PAIRS - m0);
        const uint32_t bufoff = (uint32_t)(i & 1) * BUF_SZ;

        asm volatile("cp.async.wait_group 0;" ::: "memory");
        __syncthreads();            // A[t] ready; everyone done with prior tile

        // ---- k-change: Bl -> smem, Bh -> registers via direct LDG (rare) ----
        if (k != kcur) {
            kcur = k;
            {   // fill Bl: 512 uint4 tasks / 128 threads
                const int chunk = tid & 7;
                #pragma unroll
                for (int p = 0; p < 4; p++) {
                    const int row = (p * 128 + tid) >> 3;
                    const uint4* src = (const uint4*)(g_B_lo + (size_t)k * 4096 + row * 64)
                                       + chunk;
                    *(uint4*)(smem + BL_OFF + row * ASTRIDE + chunk * 16) = *src;
                }
            }
            // Bh fragments straight from global (fragment-pattern LDG.32)
            {
                const __nv_bfloat16* bk = g_B_hi + (size_t)k * 4096;
                const int co0 = 32 * ni + (lane >> 2);
                const int cil = (lane & 3) * 2;
                #pragma unroll
                for (int kc = 0; kc < 4; kc++)
                    #pragma unroll
                    for (int np = 0; np < 2; np++) {
                        const int co = co0 + 16 * np;
                        const int ci = kc * 16 + cil;
                        bh[kc][np][0] = *(const uint32_t*)(bk + co * 64 + ci);
                        bh[kc][np][1] = *(const uint32_t*)(bk + co * 64 + ci + 8);
                        bh[kc][np][2] = *(const uint32_t*)(bk + (co + 8) * 64 + ci);
                        bh[kc][np][3] = *(const uint32_t*)(bk + (co + 8) * 64 + ci + 8);
                    }
            }
            __syncthreads();        // Bl visible before LDSM below
        }

        if (i + 1 < nt_) prefetch_A(sbase, bufoff ^ BUF_SZ, tid, nrow);
        if (i + 2 < nt_) load_nrow(imap, t + 2, tid, nrow);

        // ---- omap preload: warp rows 32mi + 4q + (lane>>3), q = 0..7 ----
        int orow[8];
        {
            const int* omk = omap + (size_t)k * M_PAIRS + m0;
            #pragma unroll
            for (int q = 0; q < 8; q++) {
                const int r = 32 * mi + 4 * q + (lane >> 3);
                orow[q] = (r < mrem) ? __ldg(&omk[r]) : -1;
            }
        }

        // ---- MMA: warp m32 x n32, 3-product bf16 split ----
        float acc[2][4][4];
        #pragma unroll
        for (int ms = 0; ms < 2; ms++)
            #pragma unroll
            for (int ng = 0; ng < 4; ng++)
                #pragma unroll
                for (int j = 0; j < 4; j++)
                    acc[ms][ng][j] = 0.f;

        #pragma unroll
        for (int kc = 0; kc < 4; kc++) {
            uint32_t ah[2][4], al[2][4], bl[2][4];
            #pragma unroll
            for (int ms = 0; ms < 2; ms++) {
                const uint32_t abase = sbase + bufoff + a_lane
                    + (32 * mi + 16 * ms) * ASTRIDE + kc * 32;
                ldsm_x4(ah[ms], abase);
                ldsm_x4(al[ms], abase + LIMB_SZ);
            }
            #pragma unroll
            for (int np = 0; np < 2; np++) {
                const uint32_t baddr = sbase + BL_OFF
                    + (32 * ni + 16 * np + b_row) * ASTRIDE + b_koff * 2 + kc * 32;
                ldsm_x4(bl[np], baddr);
            }
            #pragma unroll
            for (int ms = 0; ms < 2; ms++)
                #pragma unroll
                for (int np = 0; np < 2; np++) {
                    mma16816(acc[ms][2*np],   ah[ms], bh[kc][np][0], bh[kc][np][1]);
                    mma16816(acc[ms][2*np+1], ah[ms], bh[kc][np][2], bh[kc][np][3]);
                    mma16816(acc[ms][2*np],   al[ms], bh[kc][np][0], bh[kc][np][1]);
                    mma16816(acc[ms][2*np+1], al[ms], bh[kc][np][2], bh[kc][np][3]);
                    mma16816(acc[ms][2*np],   ah[ms], bl[np][0], bl[np][1]);
                    mma16816(acc[ms][2*np+1], ah[ms], bl[np][2], bl[np][3]);
                }
        }

        // ---- per-warp stage + scatter (two 16-row passes, warp-private) ----
        {
            const int g  = lane >> 2;
            const int tq = lane & 3;
            const int c  = lane & 7;
            const int rq = lane >> 3;
            #pragma unroll
            for (int ms = 0; ms < 2; ms++) {
                #pragma unroll
                for (int ng = 0; ng < 4; ng++) {
                    *(float2*)&swarp[g * SSTRIDE + 8 * ng + 2 * tq] =
                        make_float2(acc[ms][ng][0], acc[ms][ng][1]);
                    *(float2*)&swarp[(g + 8) * SSTRIDE + 8 * ng + 2 * tq] =
                        make_float2(acc[ms][ng][2], acc[ms][ng][3]);
                }
                __syncwarp();
                #pragma unroll
                for (int p = 0; p < 4; p++) {
                    const int q = ms * 4 + p;
                    if (orow[q] >= 0) {
                        float4 v = *(const float4*)&swarp[(4 * p + rq) * SSTRIDE + 4 * c];
                        asm volatile("red.global.add.v4.f32 [%0], {%1, %2, %3, %4};"
                                     :: "l"(out + (size_t)orow[q] * C_OUT + 32 * ni + 4 * c),
                                        "f"(v.x), "f"(v.y), "f"(v.z), "f"(v.w)
                                     : "memory");
                    }
                }
                __syncwarp();       // scatter reads done before next pass overwrites
            }
        }
    }
}

// ---------------------------------------------------------------------------
// Launch
// ---------------------------------------------------------------------------
extern "C" void kernel_launch(void* const* d_in, const int* in_sizes, int n_in,
                              void* d_out, int out_size) {
    const float* in_feats = (const float*)d_in[0];
    const float* kernel   = (const float*)d_in[1];
    const float* bias     = (const float*)d_in[2];
    const int*   imap     = (const int*)d_in[3];
    const int*   omap     = (const int*)d_in[4];
    float* out = (float*)d_out;
    (void)in_sizes; (void)n_in; (void)out_size;

    cudaFuncSetAttribute(conv_mma_kernel, cudaFuncAttributeMaxDynamicSharedMemorySize,
                         SMEM_BYTES);

    split_feats_kernel<<<4096, 256>>>(in_feats, N_IN * C_IN / 4);
    split_weights_kernel<<<(K_VOL * C_IN * C_OUT + 255) / 256, 256>>>(kernel);
    init_bias_kernel<<<2048, 256>>>(out, bias, N_OUT * C_OUT / 4);

    conv_mma_kernel<<<GRID_P, 128, SMEM_BYTES>>>(imap, omap, out);
}

// round 10
// speedup vs baseline: 3.7937x; 1.3635x over previous
#include <cuda_runtime.h>
#include <cuda_fp16.h>
#include <cstdint>

// ---------------------------------------------------------------------------
// Problem constants
// ---------------------------------------------------------------------------
#define K_VOL    27
#define M_PAIRS  100000
#define C_IN     64
#define C_OUT    64
#define N_IN     200000
#define N_OUT    200000

#define TILE_M   64
#define TILES_PER_K ((M_PAIRS + TILE_M - 1) / TILE_M)   // 1563
#define TOTAL_TILES (K_VOL * TILES_PER_K)               // 42201
#define GRID_P   740                                     // 5 blocks/SM * 148
#define BASE_T   (TOTAL_TILES / GRID_P)                  // 57
#define EXTRA_T  (TOTAL_TILES - GRID_P * BASE_T)         // 21

// fp16 scratch (device globals)
__device__ __half g_Ah[(size_t)N_IN * C_IN];            // [row][ci]  128B rows
__device__ __half g_Bh[K_VOL * C_IN * C_OUT];           // [k][co][ci]

// ---------------------------------------------------------------------------
// smem layout (bytes), per block:
//   buf0 : A 64 rows * 144 = 9216    [0, 9216)
//   buf1 :                            [9216, 18432)
//   stage: 4 warps * 16 rows * 36 floats = 9216  [18432, 27648)
// ---------------------------------------------------------------------------
#define ASTRIDE    144
#define BUF_SZ     9216
#define STAGE_OFF  18432
#define WSTAGE_SZ  2304
#define SMEM_BYTES 27648
#define SSTRIDE    36        // floats per stage row

__device__ __forceinline__ uint32_t smem_u32(const void* p) {
    uint32_t a;
    asm("{ .reg .u64 t; cvta.to.shared.u64 t, %1; cvt.u32.u64 %0, t; }" : "=r"(a) : "l"(p));
    return a;
}

__device__ __forceinline__ void ldsm_x4(uint32_t* r, uint32_t addr) {
    asm volatile("ldmatrix.sync.aligned.m8n8.x4.shared.b16 {%0,%1,%2,%3}, [%4];"
                 : "=r"(r[0]), "=r"(r[1]), "=r"(r[2]), "=r"(r[3]) : "r"(addr));
}

__device__ __forceinline__ void mma16816(float* c,
                                         const uint32_t* a, uint32_t b0, uint32_t b1) {
    asm volatile(
        "mma.sync.aligned.m16n8k16.row.col.f32.f16.f16.f32 "
        "{%0,%1,%2,%3}, {%4,%5,%6,%7}, {%8,%9}, {%0,%1,%2,%3};"
        : "+f"(c[0]), "+f"(c[1]), "+f"(c[2]), "+f"(c[3])
        : "r"(a[0]), "r"(a[1]), "r"(a[2]), "r"(a[3]), "r"(b0), "r"(b1));
}

__device__ __forceinline__ void cp_async16(uint32_t dst, const void* src, uint32_t sz) {
    asm volatile("cp.async.cg.shared.global [%0], [%1], 16, %2;"
                 :: "r"(dst), "l"(src), "r"(sz) : "memory");
}

// ---------------------------------------------------------------------------
// Kernel A: convert fp32 features -> fp16
// ---------------------------------------------------------------------------
__global__ void half_feats_kernel(const float* __restrict__ in, int total4) {
    int idx = blockIdx.x * blockDim.x + threadIdx.x;
    int stride = gridDim.x * blockDim.x;
    const float4* in4 = (const float4*)in;
    __half2* h2 = (__half2*)g_Ah;
    for (int i = idx; i < total4; i += stride) {
        float4 v = in4[i];
        h2[i * 2 + 0] = __floats2half2_rn(v.x, v.y);
        h2[i * 2 + 1] = __floats2half2_rn(v.z, v.w);
    }
}

// ---------------------------------------------------------------------------
// Kernel B: convert + transpose weights: g_Bh[k][co][ci] = fp16(W[k][ci][co])
// ---------------------------------------------------------------------------
__global__ void half_weights_kernel(const float* __restrict__ W) {
    int idx = blockIdx.x * blockDim.x + threadIdx.x;
    if (idx >= K_VOL * C_IN * C_OUT) return;
    int k  = idx / (C_IN * C_OUT);
    int r  = idx % (C_IN * C_OUT);
    int ci = r / C_OUT;
    int co = r % C_OUT;
    g_Bh[k * (C_IN * C_OUT) + co * C_IN + ci] = __float2half_rn(W[idx]);
}

// ---------------------------------------------------------------------------
// Kernel C: out[row][c] = bias[c]
// ---------------------------------------------------------------------------
__global__ void init_bias_kernel(float* __restrict__ out, const float* __restrict__ bias,
                                 int total4) {
    const float4* b4 = (const float4*)bias;
    int idx = blockIdx.x * blockDim.x + threadIdx.x;
    int stride = gridDim.x * blockDim.x;
    for (int i = idx; i < total4; i += stride)
        ((float4*)out)[i] = b4[i & 15];
}

// ---------------------------------------------------------------------------
// nrow preload + A prefetch: 512 cp.async 16B tasks (64 rows x 8 chunks)
// thread serves rows 16q + (tid>>3), q = 0..3
// ---------------------------------------------------------------------------
__device__ __forceinline__ void load_nrow(const int* __restrict__ imap, int t, int tid,
                                          int nrow[4]) {
    const int k    = t / TILES_PER_K;
    const int m0   = (t % TILES_PER_K) * TILE_M;
    const int mrem = min(TILE_M, M_PAIRS - m0);
    const int* imk = imap + (size_t)k * M_PAIRS + m0;
    #pragma unroll
    for (int q = 0; q < 4; q++) {
        const int r = q * 16 + (tid >> 3);
        nrow[q] = (r < mrem) ? __ldg(&imk[r]) : -1;
    }
}

__device__ __forceinline__ void prefetch_A(uint32_t sbase, uint32_t bufoff, int tid,
                                           const int nrow[4]) {
    const int chunk = tid & 7;
    #pragma unroll
    for (int q = 0; q < 4; q++) {
        const int row = q * 16 + (tid >> 3);
        const int gr  = nrow[q];
        const char* src = (const char*)g_Ah + ((size_t)(gr < 0 ? 0 : gr)) * 128 + chunk * 16;
        cp_async16(sbase + bufoff + row * ASTRIDE + chunk * 16, src, gr >= 0 ? 16u : 0u);
    }
    asm volatile("cp.async.commit_group;" ::: "memory");
}

// ---------------------------------------------------------------------------
// Kernel D: persistent gather -> single-fp16 HMMA -> per-warp staged scatter
// 128 threads (4 warps: 2mi x 2ni), TILE_M = 64, B entirely in registers
// ---------------------------------------------------------------------------
__global__ __launch_bounds__(128, 5)
void conv_mma_kernel(const int* __restrict__ imap, const int* __restrict__ omap,
                     float* __restrict__ out) {
    extern __shared__ char smem[];
    const uint32_t sbase = smem_u32(smem);

    const int tid  = threadIdx.x;
    const int wid  = tid >> 5;
    const int lane = tid & 31;
    const int mi   = wid >> 1;      // 0..1 : rows 32*mi..+31
    const int ni   = wid & 1;       // 0..1 : cols 32*ni..+31

    const int b   = blockIdx.x;
    const int nt_ = BASE_T + (b < EXTRA_T);
    const int t0  = b * BASE_T + min(b, EXTRA_T);

    // A ldmatrix lane mapping (proven since R5)
    const int li = lane >> 3;
    const uint32_t a_lane = (uint32_t)((((li & 1) * 8) + (lane & 7)) * ASTRIDE + (li >> 1) * 16);

    uint32_t bh[4][2][4];           // B fragments: [kc][np][4] (registers only)
    int kcur = -1;

    int nrow[4];
    load_nrow(imap, t0, tid, nrow);
    prefetch_A(sbase, 0, tid, nrow);
    if (nt_ > 1) load_nrow(imap, t0 + 1, tid, nrow);

    float* swarp = (float*)(smem + STAGE_OFF + wid * WSTAGE_SZ);

    for (int i = 0; i < nt_; i++) {
        const int t    = t0 + i;
        const int k    = t / TILES_PER_K;
        const int m0   = (t % TILES_PER_K) * TILE_M;
        const int mrem = min(TILE_M, M_PAIRS - m0);
        const uint32_t bufoff = (uint32_t)(i & 1) * BUF_SZ;

        asm volatile("cp.async.wait_group 0;" ::: "memory");
        __syncthreads();            // A[t] ready; all warps done LDSM-ing prior buf

        // ---- k-change: B fragments straight from global into registers ----
        // (in-thread dependency; no block sync needed)
        if (k != kcur) {
            kcur = k;
            const __half* bk = g_Bh + (size_t)k * 4096;
            const int co0 = 32 * ni + (lane >> 2);
            const int cil = (lane & 3) * 2;
            #pragma unroll
            for (int kc = 0; kc < 4; kc++)
                #pragma unroll
                for (int np = 0; np < 2; np++) {
                    const int co = co0 + 16 * np;
                    const int ci = kc * 16 + cil;
                    bh[kc][np][0] = *(const uint32_t*)(bk + co * 64 + ci);
                    bh[kc][np][1] = *(const uint32_t*)(bk + co * 64 + ci + 8);
                    bh[kc][np][2] = *(const uint32_t*)(bk + (co + 8) * 64 + ci);
                    bh[kc][np][3] = *(const uint32_t*)(bk + (co + 8) * 64 + ci + 8);
                }
        }

        if (i + 1 < nt_) prefetch_A(sbase, bufoff ^ BUF_SZ, tid, nrow);
        if (i + 2 < nt_) load_nrow(imap, t + 2, tid, nrow);

        // ---- omap preload: warp rows 32mi + 4q + (lane>>3), q = 0..7 ----
        int orow[8];
        {
            const int* omk = omap + (size_t)k * M_PAIRS + m0;
            #pragma unroll
            for (int q = 0; q < 8; q++) {
                const int r = 32 * mi + 4 * q + (lane >> 3);
                orow[q] = (r < mrem) ? __ldg(&omk[r]) : -1;
            }
        }

        // ---- MMA: warp m32 x n32, single fp16 product ----
        float acc[2][4][4];
        #pragma unroll
        for (int ms = 0; ms < 2; ms++)
            #pragma unroll
            for (int ng = 0; ng < 4; ng++)
                #pragma unroll
                for (int j = 0; j < 4; j++)
                    acc[ms][ng][j] = 0.f;

        #pragma unroll
        for (int kc = 0; kc < 4; kc++) {
            uint32_t ah[2][4];
            #pragma unroll
            for (int ms = 0; ms < 2; ms++) {
                const uint32_t abase = sbase + bufoff + a_lane
                    + (32 * mi + 16 * ms) * ASTRIDE + kc * 32;
                ldsm_x4(ah[ms], abase);
            }
            #pragma unroll
            for (int ms = 0; ms < 2; ms++)
                #pragma unroll
                for (int np = 0; np < 2; np++) {
                    mma16816(acc[ms][2*np],   ah[ms], bh[kc][np][0], bh[kc][np][1]);
                    mma16816(acc[ms][2*np+1], ah[ms], bh[kc][np][2], bh[kc][np][3]);
                }
        }

        // ---- per-warp stage + scatter (two 16-row passes, warp-private) ----
        {
            const int g  = lane >> 2;
            const int tq = lane & 3;
            const int c  = lane & 7;
            const int rq = lane >> 3;
            #pragma unroll
            for (int ms = 0; ms < 2; ms++) {
                #pragma unroll
                for (int ng = 0; ng < 4; ng++) {
                    *(float2*)&swarp[g * SSTRIDE + 8 * ng + 2 * tq] =
                        make_float2(acc[ms][ng][0], acc[ms][ng][1]);
                    *(float2*)&swarp[(g + 8) * SSTRIDE + 8 * ng + 2 * tq] =
                        make_float2(acc[ms][ng][2], acc[ms][ng][3]);
                }
                __syncwarp();
                #pragma unroll
                for (int p = 0; p < 4; p++) {
                    const int q = ms * 4 + p;
                    if (orow[q] >= 0) {
                        float4 v = *(const float4*)&swarp[(4 * p + rq) * SSTRIDE + 4 * c];
                        asm volatile("red.global.add.v4.f32 [%0], {%1, %2, %3, %4};"
                                     :: "l"(out + (size_t)orow[q] * C_OUT + 32 * ni + 4 * c),
                                        "f"(v.x), "f"(v.y), "f"(v.z), "f"(v.w)
                                     : "memory");
                    }
                }
                __syncwarp();       // scatter reads done before next pass overwrites
            }
        }
    }
}

// ---------------------------------------------------------------------------
// Launch
// ---------------------------------------------------------------------------
extern "C" void kernel_launch(void* const* d_in, const int* in_sizes, int n_in,
                              void* d_out, int out_size) {
    const float* in_feats = (const float*)d_in[0];
    const float* kernel   = (const float*)d_in[1];
    const float* bias     = (const float*)d_in[2];
    const int*   imap     = (const int*)d_in[3];
    const int*   omap     = (const int*)d_in[4];
    float* out = (float*)d_out;
    (void)in_sizes; (void)n_in; (void)out_size;

    cudaFuncSetAttribute(conv_mma_kernel, cudaFuncAttributeMaxDynamicSharedMemorySize,
                         SMEM_BYTES);

    half_feats_kernel<<<4096, 256>>>(in_feats, N_IN * C_IN / 4);
    half_weights_kernel<<<(K_VOL * C_IN * C_OUT + 255) / 256, 256>>>(kernel);
    init_bias_kernel<<<2048, 256>>>(out, bias, N_OUT * C_OUT / 4);

    conv_mma_kernel<<<GRID_P, 128, SMEM_BYTES>>>(imap, omap, out);
}

// round 14
// speedup vs baseline: 4.2596x; 1.1228x over previous
#include <cuda_runtime.h>
#include <cuda_fp16.h>
#include <cstdint>

// ---------------------------------------------------------------------------
// Problem constants
// ---------------------------------------------------------------------------
#define K_VOL    27
#define M_PAIRS  100000
#define C_IN     64
#define C_OUT    64
#define N_IN     200000
#define N_OUT    200000

#define TILE_M   64
#define TILES_PER_K ((M_PAIRS + TILE_M - 1) / TILE_M)   // 1563
#define TOTAL_TILES (K_VOL * TILES_PER_K)               // 42201
#define GRID_P   740                                     // 5 blocks/SM * 148
#define BASE_T   (TOTAL_TILES / GRID_P)                  // 57
#define EXTRA_T  (TOTAL_TILES - GRID_P * BASE_T)         // 21

// fp16 scratch (device globals)
__device__ __half g_Ah[(size_t)N_IN * C_IN];            // [row][ci]  128B rows
__device__ __half g_Bh[K_VOL * C_IN * C_OUT];           // [k][co][ci]

// ---------------------------------------------------------------------------
// smem layout (bytes), per block:
//   buf0 : A 64 rows * 144 = 9216     [0, 9216)
//   buf1 :                             [9216, 18432)
//   stage: 4 warps * 16 rows * 80B     [18432, 23552)   (fp16, stride 80)
// ---------------------------------------------------------------------------
#define ASTRIDE    144
#define BUF_SZ     9216
#define STAGE_OFF  18432
#define WSTAGE_SZ  1280      // 16 rows * 80 B
#define SROW       80        // stage row stride (bytes); words 20g+tq conflict-free
#define SMEM_BYTES 23552

__device__ __forceinline__ uint32_t smem_u32(const void* p) {
    uint32_t a;
    asm("{ .reg .u64 t; cvta.to.shared.u64 t, %1; cvt.u32.u64 %0, t; }" : "=r"(a) : "l"(p));
    return a;
}

__device__ __forceinline__ void ldsm_x4(uint32_t* r, uint32_t addr) {
    asm volatile("ldmatrix.sync.aligned.m8n8.x4.shared.b16 {%0,%1,%2,%3}, [%4];"
                 : "=r"(r[0]), "=r"(r[1]), "=r"(r[2]), "=r"(r[3]) : "r"(addr));
}

__device__ __forceinline__ void mma16816(float* c,
                                         const uint32_t* a, uint32_t b0, uint32_t b1) {
    asm volatile(
        "mma.sync.aligned.m16n8k16.row.col.f32.f16.f16.f32 "
        "{%0,%1,%2,%3}, {%4,%5,%6,%7}, {%8,%9}, {%0,%1,%2,%3};"
        : "+f"(c[0]), "+f"(c[1]), "+f"(c[2]), "+f"(c[3])
        : "r"(a[0]), "r"(a[1]), "r"(a[2]), "r"(a[3]), "r"(b0), "r"(b1));
}

__device__ __forceinline__ void cp_async16(uint32_t dst, const void* src, uint32_t sz) {
    asm volatile("cp.async.cg.shared.global [%0], [%1], 16, %2;"
                 :: "r"(dst), "l"(src), "r"(sz) : "memory");
}

// ---------------------------------------------------------------------------
// Fused preprocessing: feats->fp16, out=bias, weights->fp16 transposed
// ---------------------------------------------------------------------------
#define FEAT4 (N_IN * C_IN / 4)      // 3,200,000 float4 tasks
#define BIAS4 (N_OUT * C_OUT / 4)    // 3,200,000 float4 tasks
#define WELEM (K_VOL * C_IN * C_OUT) // 110,592 scalar tasks
#define PREP_TOTAL (FEAT4 + BIAS4 + WELEM)

__global__ void prep_kernel(const float* __restrict__ in_feats,
                            const float* __restrict__ W,
                            const float* __restrict__ bias,
                            float* __restrict__ out) {
    int idx = blockIdx.x * blockDim.x + threadIdx.x;
    int stride = gridDim.x * blockDim.x;
    const float4* in4 = (const float4*)in_feats;
    const float4* b4  = (const float4*)bias;
    float4* out4 = (float4*)out;
    __half2* h2 = (__half2*)g_Ah;
    for (int i = idx; i < PREP_TOTAL; i += stride) {
        if (i < FEAT4) {
            float4 v = in4[i];
            h2[i * 2 + 0] = __floats2half2_rn(v.x, v.y);
            h2[i * 2 + 1] = __floats2half2_rn(v.z, v.w);
        } else if (i < FEAT4 + BIAS4) {
            const int j = i - FEAT4;
            out4[j] = b4[j & 15];
        } else {
            const int e = i - FEAT4 - BIAS4;
            const int k = e >> 12, r = e & 4095, ci = r >> 6, co = r & 63;
            g_Bh[k * 4096 + co * 64 + ci] = __float2half_rn(W[e]);
        }
    }
}

// ---------------------------------------------------------------------------
// nrow preload + A prefetch: 512 cp.async 16B tasks (64 rows x 8 chunks)
// ---------------------------------------------------------------------------
__device__ __forceinline__ void load_nrow(const int* __restrict__ imap, int t, int tid,
                                          int nrow[4]) {
    const int k    = t / TILES_PER_K;
    const int m0   = (t % TILES_PER_K) * TILE_M;
    const int mrem = min(TILE_M, M_PAIRS - m0);
    const int* imk = imap + (size_t)k * M_PAIRS + m0;
    #pragma unroll
    for (int q = 0; q < 4; q++) {
        const int r = q * 16 + (tid >> 3);
        nrow[q] = (r < mrem) ? __ldg(&imk[r]) : -1;
    }
}

__device__ __forceinline__ void prefetch_A(uint32_t sbase, uint32_t bufoff, int tid,
                                           const int nrow[4]) {
    const int chunk = tid & 7;
    #pragma unroll
    for (int q = 0; q < 4; q++) {
        const int row = q * 16 + (tid >> 3);
        const int gr  = nrow[q];
        const char* src = (const char*)g_Ah + ((size_t)(gr < 0 ? 0 : gr)) * 128 + chunk * 16;
        cp_async16(sbase + bufoff + row * ASTRIDE + chunk * 16, src, gr >= 0 ? 16u : 0u);
    }
    asm volatile("cp.async.commit_group;" ::: "memory");
}

// ---------------------------------------------------------------------------
// Kernel D: persistent gather -> fp16 HMMA -> fp16-staged red.v4 scatter
// 128 threads (4 warps: 2mi x 2ni), TILE_M = 64, B in registers
// ---------------------------------------------------------------------------
__global__ __launch_bounds__(128, 5)
void conv_mma_kernel(const int* __restrict__ imap, const int* __restrict__ omap,
                     float* __restrict__ out) {
    extern __shared__ char smem[];
    const uint32_t sbase = smem_u32(smem);

    const int tid  = threadIdx.x;
    const int wid  = tid >> 5;
    const int lane = tid & 31;
    const int mi   = wid >> 1;      // 0..1 : rows 32*mi..+31
    const int ni   = wid & 1;       // 0..1 : cols 32*ni..+31

    const int b   = blockIdx.x;
    const int nt_ = BASE_T + (b < EXTRA_T);
    const int t0  = b * BASE_T + min(b, EXTRA_T);

    // A ldmatrix lane mapping (proven since R5)
    const int li = lane >> 3;
    const uint32_t a_lane = (uint32_t)((((li & 1) * 8) + (lane & 7)) * ASTRIDE + (li >> 1) * 16);

    uint32_t bh[4][2][4];           // B fragments: [kc][np][4] (registers only)
    int kcur = -1;

    int nrow[4];
    load_nrow(imap, t0, tid, nrow);
    prefetch_A(sbase, 0, tid, nrow);
    if (nt_ > 1) load_nrow(imap, t0 + 1, tid, nrow);

    char* swarp = smem + STAGE_OFF + wid * WSTAGE_SZ;

    for (int i = 0; i < nt_; i++) {
        const int t    = t0 + i;
        const int k    = t / TILES_PER_K;
        const int m0   = (t % TILES_PER_K) * TILE_M;
        const int mrem = min(TILE_M, M_PAIRS - m0);
        const uint32_t bufoff = (uint32_t)(i & 1) * BUF_SZ;

        asm volatile("cp.async.wait_group 0;" ::: "memory");
        __syncthreads();            // A[t] ready; all warps done with prior buf

        // ---- k-change: B fragments straight from global into registers ----
        if (k != kcur) {
            kcur = k;
            const __half* bk = g_Bh + (size_t)k * 4096;
            const int co0 = 32 * ni + (lane >> 2);
            const int cil = (lane & 3) * 2;
            #pragma unroll
            for (int kc = 0; kc < 4; kc++)
                #pragma unroll
                for (int np = 0; np < 2; np++) {
                    const int co = co0 + 16 * np;
                    const int ci = kc * 16 + cil;
                    bh[kc][np][0] = *(const uint32_t*)(bk + co * 64 + ci);
                    bh[kc][np][1] = *(const uint32_t*)(bk + co * 64 + ci + 8);
                    bh[kc][np][2] = *(const uint32_t*)(bk + (co + 8) * 64 + ci);
                    bh[kc][np][3] = *(const uint32_t*)(bk + (co + 8) * 64 + ci + 8);
                }
        }

        if (i + 1 < nt_) prefetch_A(sbase, bufoff ^ BUF_SZ, tid, nrow);
        if (i + 2 < nt_) load_nrow(imap, t + 2, tid, nrow);

        // ---- omap preload: warp rows 32mi + 4q + (lane>>3), q = 0..7 ----
        int orow[8];
        {
            const int* omk = omap + (size_t)k * M_PAIRS + m0;
            #pragma unroll
            for (int q = 0; q < 8; q++) {
                const int r = 32 * mi + 4 * q + (lane >> 3);
                orow[q] = (r < mrem) ? __ldg(&omk[r]) : -1;
            }
        }

        // ---- MMA: warp m32 x n32, single fp16 product ----
        float acc[2][4][4];
        #pragma unroll
        for (int ms = 0; ms < 2; ms++)
            #pragma unroll
            for (int ng = 0; ng < 4; ng++)
                #pragma unroll
                for (int j = 0; j < 4; j++)
                    acc[ms][ng][j] = 0.f;

        #pragma unroll
        for (int kc = 0; kc < 4; kc++) {
            uint32_t ah[2][4];
            #pragma unroll
            for (int ms = 0; ms < 2; ms++) {
                const uint32_t abase = sbase + bufoff + a_lane
                    + (32 * mi + 16 * ms) * ASTRIDE + kc * 32;
                ldsm_x4(ah[ms], abase);
            }
            #pragma unroll
            for (int ms = 0; ms < 2; ms++)
                #pragma unroll
                for (int np = 0; np < 2; np++) {
                    mma16816(acc[ms][2*np],   ah[ms], bh[kc][np][0], bh[kc][np][1]);
                    mma16816(acc[ms][2*np+1], ah[ms], bh[kc][np][2], bh[kc][np][3]);
                }
        }

        // ---- per-warp fp16 stage + scatter (two 16-row passes) ----
        {
            const int g  = lane >> 2;       // 0..7
            const int tq = lane & 3;        // 0..3
            const int c  = lane & 7;        // 0..7  (16B col group in out row)
            const int rq = lane >> 3;       // 0..3
            #pragma unroll
            for (int ms = 0; ms < 2; ms++) {
                // stage write: half2 at (row g / g+8, local col 8ng+2tq)
                #pragma unroll
                for (int ng = 0; ng < 4; ng++) {
                    *(__half2*)(swarp + g * SROW + 16 * ng + 4 * tq) =
                        __floats2half2_rn(acc[ms][ng][0], acc[ms][ng][1]);
                    *(__half2*)(swarp + (g + 8) * SROW + 16 * ng + 4 * tq) =
                        __floats2half2_rn(acc[ms][ng][2], acc[ms][ng][3]);
                }
                __syncwarp();
                // scatter: rows 4p+rq, local cols 4c..4c+3 (8B fp16 -> 4 f32)
                #pragma unroll
                for (int p = 0; p < 4; p++) {
                    const int q = ms * 4 + p;
                    if (orow[q] >= 0) {
                        uint2 hv = *(const uint2*)(swarp + (4 * p + rq) * SROW + 8 * c);
                        float2 lo = __half22float2(*(__half2*)&hv.x);
                        float2 hi = __half22float2(*(__half2*)&hv.y);
                        asm volatile("red.global.add.v4.f32 [%0], {%1, %2, %3, %4};"
                                     :: "l"(out + (size_t)orow[q] * C_OUT + 32 * ni + 4 * c),
                                        "f"(lo.x), "f"(lo.y), "f"(hi.x), "f"(hi.y)
                                     : "memory");
                    }
                }
                __syncwarp();       // reads done before next pass overwrites
            }
        }
    }
}

// ---------------------------------------------------------------------------
// Launch
// ---------------------------------------------------------------------------
extern "C" void kernel_launch(void* const* d_in, const int* in_sizes, int n_in,
                              void* d_out, int out_size) {
    const float* in_feats = (const float*)d_in[0];
    const float* kernel   = (const float*)d_in[1];
    const float* bias     = (const float*)d_in[2];
    const int*   imap     = (const int*)d_in[3];
    const int*   omap     = (const int*)d_in[4];
    float* out = (float*)d_out;
    (void)in_sizes; (void)n_in; (void)out_size;

    cudaFuncSetAttribute(conv_mma_kernel, cudaFuncAttributeMaxDynamicSharedMemorySize,
                         SMEM_BYTES);

    prep_kernel<<<6360, 256>>>(in_feats, kernel, bias, out);
    conv_mma_kernel<<<GRID_P, 128, SMEM_BYTES>>>(imap, omap, out);
}